// round 11
// baseline (speedup 1.0000x reference)
#include <cuda_runtime.h>
#include <math.h>

#define DMODEL 1024
#define SEQ    2048
#define BATCH  2
#define NHEADS 16
#define HDIM   64
#define MTOK   (BATCH*SEQ)   // 4096
#define DFF    (4*DMODEL)    // 4096
#define LN_EPS 1e-9f

// ---------------- scratch (device globals: allocation-free) ----------------
__device__ float g_ln [MTOK*DMODEL];
__device__ float g_q  [MTOK*DMODEL];
__device__ float g_k  [MTOK*DMODEL];
__device__ float g_v  [MTOK*DMODEL];
__device__ float g_pre[MTOK*DMODEL];
__device__ float g_x1 [MTOK*DMODEL];
__device__ float g_mid[MTOK*DFF];
// tf32-rounded weights
__device__ float g_wq[DMODEL*DMODEL];
__device__ float g_wk[DMODEL*DMODEL];
__device__ float g_wv[DMODEL*DMODEL];
__device__ float g_wo[DMODEL*DMODEL];
__device__ float g_wu[DFF*DMODEL];
__device__ float g_wd[DMODEL*DFF];

// ---------------- helpers ----------------
__device__ __forceinline__ float gelu_exact(float x) {
    return 0.5f * x * (1.f + erff(x * 0.70710678118654752f));
}
__device__ __forceinline__ unsigned f2tf32(float f) {
    unsigned u;
    asm("cvt.rna.tf32.f32 %0, %1;" : "=r"(u) : "f"(f));
    return u;
}
__device__ __forceinline__ float rndtf32(float f) {
    return __uint_as_float(f2tf32(f));
}
__device__ __forceinline__ void mma_tf32(float c[4],
    unsigned a0, unsigned a1, unsigned a2, unsigned a3,
    unsigned b0, unsigned b1)
{
    asm volatile(
        "mma.sync.aligned.m16n8k8.row.col.f32.tf32.tf32.f32 "
        "{%0,%1,%2,%3}, {%4,%5,%6,%7}, {%8,%9}, {%0,%1,%2,%3};\n"
        : "+f"(c[0]), "+f"(c[1]), "+f"(c[2]), "+f"(c[3])
        : "r"(a0), "r"(a1), "r"(a2), "r"(a3), "r"(b0), "r"(b1));
}
__device__ __forceinline__ void ldsm4(unsigned &r0, unsigned &r1,
                                      unsigned &r2, unsigned &r3, unsigned addr)
{
    asm volatile("ldmatrix.sync.aligned.m8n8.x4.shared.b16 {%0,%1,%2,%3}, [%4];"
        : "=r"(r0), "=r"(r1), "=r"(r2), "=r"(r3) : "r"(addr));
}
__device__ __forceinline__ unsigned smem_u32(const void* p) {
    return (unsigned)__cvta_generic_to_shared(p);
}
__device__ __forceinline__ void cpasync16(unsigned dst, const void* src) {
    asm volatile("cp.async.cg.shared.global [%0], [%1], 16;" :: "r"(dst), "l"(src));
}
#define CP_COMMIT asm volatile("cp.async.commit_group;")
#define CP_WAIT0  asm volatile("cp.async.wait_group 0;")
#define CP_WAIT1  asm volatile("cp.async.wait_group 1;")

// ---------------- weight pre-round (rna -> tf32 bit pattern) ----------------
__global__ void __launch_bounds__(256) round_tf32_kernel(
    const float4* __restrict__ src, float4* __restrict__ dst, int n4)
{
    int i = blockIdx.x * 256 + threadIdx.x;
    if (i < n4) {
        float4 v = src[i];
        v.x = rndtf32(v.x); v.y = rndtf32(v.y);
        v.z = rndtf32(v.z); v.w = rndtf32(v.w);
        dst[i] = v;
    }
}

// ---------------- LayerNorm (ddof=1, eps inside sqrt), tf32-rounded out ----
__global__ void __launch_bounds__(256) ln_kernel(
    const float* __restrict__ x,
    const float* __restrict__ msc,
    const float* __restrict__ ssc,
    float* __restrict__ out)
{
    __shared__ float xs[DMODEL];
    __shared__ float rs[16];
    int row = blockIdx.x;
    const float* xr = x + (size_t)row * DMODEL;
    float s = 0.f, s2 = 0.f;
    #pragma unroll
    for (int i = threadIdx.x; i < DMODEL; i += 256) {
        float v = xr[i]; xs[i] = v; s += v; s2 += v * v;
    }
    #pragma unroll
    for (int o = 16; o > 0; o >>= 1) {
        s  += __shfl_down_sync(0xffffffffu, s,  o);
        s2 += __shfl_down_sync(0xffffffffu, s2, o);
    }
    int wid = threadIdx.x >> 5;
    if ((threadIdx.x & 31) == 0) { rs[wid] = s; rs[8 + wid] = s2; }
    __syncthreads();
    s = 0.f; s2 = 0.f;
    #pragma unroll
    for (int w = 0; w < 8; w++) { s += rs[w]; s2 += rs[8 + w]; }
    float mean = s * (1.f / DMODEL);
    float var  = (s2 - (float)DMODEL * mean * mean) * (1.f / (DMODEL - 1));
    float inv  = rsqrtf(var + LN_EPS);
    float* outr = out + (size_t)row * DMODEL;
    #pragma unroll
    for (int i = threadIdx.x; i < DMODEL; i += 256)
        outr[i] = rndtf32((xs[i] - mean) * inv * ssc[i] + msc[i]);
}

// ---------------- TF32 GEMM  C = A(MxK)*W(NxK)^T [+Res][+GELU] -------------
// 128x128x32 CTA tile, 4 warps of 64x64 (2x2), 3-stage cp.async, occ 2.
#define GBM 128
#define GBN 128
#define GBK 32
#define GBKP 36
#define GAB (GBM*GBKP)
#define GBB (GBN*GBKP)
#define NSTG 3
#define GEMM_SMEM (NSTG*(GAB+GBB)*4)

template<int GELU, int ROUND>
__global__ void __launch_bounds__(128, 2) gemm_tf32_kernel(
    const float* __restrict__ A, const float* __restrict__ W,
    const float* __restrict__ Res, float* __restrict__ C,
    int M, int N, int K)
{
    extern __shared__ unsigned gsm[];
    unsigned* As = gsm;                  // [NSTG][GAB]
    unsigned* Bs = gsm + NSTG * GAB;     // [NSTG][GBB]

    int bm = blockIdx.y * GBM, bn = blockIdx.x * GBN;
    int tid = threadIdx.x, lane = tid & 31, wid = tid >> 5;
    int m_base = (wid & 1) * 64;
    int n_base = (wid >> 1) * 64;

    int lr = tid >> 1;               // 0..63 (rows lr and lr+64)
    int lk = (tid & 1) * 16;         // 0 or 16
    const float* Ag = A + (size_t)(bm + lr) * K + lk;
    const float* Wg = W + (size_t)(bn + lr) * K + lk;
    unsigned aDst = smem_u32(As) + ((lr * GBKP + lk) << 2);
    unsigned bDst = smem_u32(Bs) + ((lr * GBKP + lk) << 2);

    unsigned aAddr0 = smem_u32(As) +
        (((m_base + (lane & 15)) * GBKP + ((lane >> 4) << 2)) << 2);
    unsigned bAddr0 = smem_u32(Bs) +
        (((n_base + (lane & 7) + (((lane >> 4) & 1) << 3)) * GBKP + (((lane >> 3) & 1) << 2)) << 2);

    float acc[4][8][4];
    #pragma unroll
    for (int mt = 0; mt < 4; mt++)
        #pragma unroll
        for (int nt = 0; nt < 8; nt++)
            #pragma unroll
            for (int e = 0; e < 4; e++) acc[mt][nt][e] = 0.f;

    int ntiles = K / GBK;
    const int halfA = 64 * K;            // element stride for +64 rows (gmem)
    const int halfS = (64 * GBKP) << 2;  // byte stride for +64 rows (smem)

    // prologue: stage tiles 0 and 1
    #pragma unroll
    for (int s = 0; s < 2; s++) {
        int koff = s * GBK;
        unsigned aD = aDst + s * (GAB * 4);
        unsigned bD = bDst + s * (GBB * 4);
        #pragma unroll
        for (int h = 0; h < 2; h++) {
            #pragma unroll
            for (int i = 0; i < 4; i++) {
                cpasync16(aD + h * halfS + i * 16, Ag + h * halfA + koff + i * 4);
                cpasync16(bD + h * halfS + i * 16, Wg + h * halfA + koff + i * 4);
            }
        }
        CP_COMMIT;
    }

    for (int kb = 0; kb < ntiles; kb++) {
        CP_WAIT1;          // tile kb landed (<=1 group pending)
        __syncthreads();   // visible block-wide; buf (kb+2)%3 reads finished

        if (kb + 2 < ntiles) {           // prefetch kb+2
            int st = (kb + 2) % NSTG;
            int koff = (kb + 2) * GBK;
            unsigned aD = aDst + st * (GAB * 4);
            unsigned bD = bDst + st * (GBB * 4);
            #pragma unroll
            for (int h = 0; h < 2; h++) {
                #pragma unroll
                for (int i = 0; i < 4; i++) {
                    cpasync16(aD + h * halfS + i * 16, Ag + h * halfA + koff + i * 4);
                    cpasync16(bD + h * halfS + i * 16, Wg + h * halfA + koff + i * 4);
                }
            }
        }
        CP_COMMIT;

        int cur = kb % NSTG;
        unsigned aC = aAddr0 + cur * (GAB * 4);
        unsigned bC = bAddr0 + cur * (GBB * 4);
        #pragma unroll
        for (int ks = 0; ks < 4; ks++) {
            unsigned a[4][4];
            #pragma unroll
            for (int mt = 0; mt < 4; mt++)
                ldsm4(a[mt][0], a[mt][1], a[mt][2], a[mt][3],
                      aC + ((mt * 16 * GBKP + ks * 8) << 2));
            #pragma unroll
            for (int ntp = 0; ntp < 4; ntp++) {
                unsigned b0, b1, b2, b3;
                ldsm4(b0, b1, b2, b3, bC + ((ntp * 16 * GBKP + ks * 8) << 2));
                #pragma unroll
                for (int mt = 0; mt < 4; mt++) {
                    mma_tf32(acc[mt][2 * ntp + 0], a[mt][0], a[mt][1], a[mt][2], a[mt][3], b0, b1);
                    mma_tf32(acc[mt][2 * ntp + 1], a[mt][0], a[mt][1], a[mt][2], a[mt][3], b2, b3);
                }
            }
        }
    }

    int er = lane >> 2, ec = (lane & 3) * 2;
    #pragma unroll
    for (int mt = 0; mt < 4; mt++) {
        #pragma unroll
        for (int nt = 0; nt < 8; nt++) {
            int row = bm + m_base + mt * 16 + er;
            int col = bn + n_base + nt * 8 + ec;
            #pragma unroll
            for (int half = 0; half < 2; half++) {
                int r2 = row + half * 8;
                float2 v;
                v.x = acc[mt][nt][half * 2 + 0];
                v.y = acc[mt][nt][half * 2 + 1];
                if (Res) {
                    float2 rr = *(const float2*)(Res + (size_t)r2 * N + col);
                    v.x += rr.x; v.y += rr.y;
                }
                if (GELU) { v.x = gelu_exact(v.x); v.y = gelu_exact(v.y); }
                if (ROUND) { v.x = rndtf32(v.x); v.y = rndtf32(v.y); }
                *(float2*)(C + (size_t)r2 * N + col) = v;
            }
        }
    }
}

// ---------------- Flash attention, TF32 tensor cores + ldmatrix + cp.async ----
#define ASTR 68
#define ATT_SMEM (3*64*ASTR*4)

__global__ void __launch_bounds__(128) attn_mma_kernel(
    const float* __restrict__ Q, const float* __restrict__ K,
    const float* __restrict__ V, float* __restrict__ O)
{
    extern __shared__ unsigned sm[];
    unsigned* Qs = sm;                 // 64*68 (Q, later P)
    unsigned* Ks = sm + 64 * ASTR;
    unsigned* Vs = sm + 2 * 64 * ASTR; // [d][key]

    int qt = gridDim.x - 1 - blockIdx.x;   // heavy tiles first
    int bh = blockIdx.y;
    int b = bh >> 4, h = bh & 15;
    int tid = threadIdx.x, lane = tid & 31, w = tid >> 5;
    int fr = lane >> 2, fc = lane & 3;

    const float* Qp = Q + (size_t)b * SEQ * DMODEL + h * HDIM;
    const float* Kp = K + (size_t)b * SEQ * DMODEL + h * HDIM;
    const float* Vp = V + (size_t)b * SEQ * DMODEL + h * HDIM;
    float*       Op = O + (size_t)b * SEQ * DMODEL + h * HDIM;

    unsigned aSel = ((lane & 15) * ASTR + ((lane >> 4) << 2)) << 2;
    unsigned bSel = (((lane & 7) + (((lane >> 4) & 1) << 3)) * ASTR
                     + (((lane >> 3) & 1) << 2)) << 2;
    unsigned qAddr = smem_u32(Qs) + ((w * 16 * ASTR) << 2) + aSel;
    unsigned kAddr = smem_u32(Ks) + bSel;
    unsigned vAddr = smem_u32(Vs) + bSel;

    int ldr = tid >> 1, ldc = (tid & 1) * 32;
    unsigned kDst = smem_u32(Ks) + ((ldr * ASTR + ldc) << 2);

    // load Q tile (scaled by 1/sqrt(64) — exact power of two, stays tf32)
    {
        const float* qp = Qp + (size_t)(qt * 64 + ldr) * DMODEL + ldc;
        unsigned* qs = Qs + ldr * ASTR + ldc;
        #pragma unroll
        for (int i = 0; i < 8; i++) {
            float4 v = *(const float4*)(qp + i * 4);
            qs[i * 4 + 0] = __float_as_uint(v.x * 0.125f);
            qs[i * 4 + 1] = __float_as_uint(v.y * 0.125f);
            qs[i * 4 + 2] = __float_as_uint(v.z * 0.125f);
            qs[i * 4 + 3] = __float_as_uint(v.w * 0.125f);
        }
    }
    __syncthreads();

    unsigned qa[8][4];
    #pragma unroll
    for (int ks = 0; ks < 8; ks++)
        ldsm4(qa[ks][0], qa[ks][1], qa[ks][2], qa[ks][3], qAddr + ((ks * 8) << 2));

    float o[8][4];
    #pragma unroll
    for (int nt = 0; nt < 8; nt++)
        #pragma unroll
        for (int e = 0; e < 4; e++) o[nt][e] = 0.f;
    float mrun0 = -INFINITY, mrun1 = -INFINITY, l0 = 0.f, l1 = 0.f;

    unsigned* prow = Qs + (w * 16 + fr) * ASTR;

    for (int kt = 0; kt <= qt; kt++) {
        __syncthreads();
        // K tile via cp.async (overlaps with V transpose below)
        {
            const float* kp = Kp + (size_t)(kt * 64 + ldr) * DMODEL + ldc;
            #pragma unroll
            for (int i = 0; i < 8; i++)
                cpasync16(kDst + i * 16, kp + i * 4);
            CP_COMMIT;
        }
        // V tile transposed: Vs[d][key]
        {
            int key = tid & 63;
            int dh = (tid >> 6) * 32;
            const float* vp = Vp + (size_t)(kt * 64 + key) * DMODEL;
            #pragma unroll
            for (int i = 0; i < 8; i++) {
                int d0 = dh + i * 4;
                float4 v = *(const float4*)(vp + d0);
                Vs[(d0 + 0) * ASTR + key] = __float_as_uint(v.x);
                Vs[(d0 + 1) * ASTR + key] = __float_as_uint(v.y);
                Vs[(d0 + 2) * ASTR + key] = __float_as_uint(v.z);
                Vs[(d0 + 3) * ASTR + key] = __float_as_uint(v.w);
            }
        }
        CP_WAIT0;
        __syncthreads();

        // S = Q @ K^T
        float sc[8][4];
        #pragma unroll
        for (int nt = 0; nt < 8; nt++)
            #pragma unroll
            for (int e = 0; e < 4; e++) sc[nt][e] = 0.f;
        #pragma unroll
        for (int ks = 0; ks < 8; ks++) {
            #pragma unroll
            for (int ntp = 0; ntp < 4; ntp++) {
                unsigned b0, b1, b2, b3;
                ldsm4(b0, b1, b2, b3, kAddr + ((ntp * 16 * ASTR + ks * 8) << 2));
                mma_tf32(sc[2 * ntp + 0], qa[ks][0], qa[ks][1], qa[ks][2], qa[ks][3], b0, b1);
                mma_tf32(sc[2 * ntp + 1], qa[ks][0], qa[ks][1], qa[ks][2], qa[ks][3], b2, b3);
            }
        }

        // causal mask on diagonal tile
        if (kt == qt) {
            int r0 = w * 16 + fr, r1 = r0 + 8;
            #pragma unroll
            for (int nt = 0; nt < 8; nt++) {
                int c0 = nt * 8 + 2 * fc;
                if (c0     > r0) sc[nt][0] = -INFINITY;
                if (c0 + 1 > r0) sc[nt][1] = -INFINITY;
                if (c0     > r1) sc[nt][2] = -INFINITY;
                if (c0 + 1 > r1) sc[nt][3] = -INFINITY;
            }
        }

        // online softmax
        float m0 = -INFINITY, m1 = -INFINITY;
        #pragma unroll
        for (int nt = 0; nt < 8; nt++) {
            m0 = fmaxf(m0, fmaxf(sc[nt][0], sc[nt][1]));
            m1 = fmaxf(m1, fmaxf(sc[nt][2], sc[nt][3]));
        }
        m0 = fmaxf(m0, __shfl_xor_sync(0xffffffffu, m0, 1));
        m0 = fmaxf(m0, __shfl_xor_sync(0xffffffffu, m0, 2));
        m1 = fmaxf(m1, __shfl_xor_sync(0xffffffffu, m1, 1));
        m1 = fmaxf(m1, __shfl_xor_sync(0xffffffffu, m1, 2));
        float mn0 = fmaxf(mrun0, m0), mn1 = fmaxf(mrun1, m1);
        float corr0 = __expf(mrun0 - mn0), corr1 = __expf(mrun1 - mn1);
        l0 *= corr0; l1 *= corr1;
        #pragma unroll
        for (int nt = 0; nt < 8; nt++) {
            o[nt][0] *= corr0; o[nt][1] *= corr0;
            o[nt][2] *= corr1; o[nt][3] *= corr1;
        }
        #pragma unroll
        for (int nt = 0; nt < 8; nt++) {
            float p0 = __expf(sc[nt][0] - mn0);
            float p1 = __expf(sc[nt][1] - mn0);
            float p2 = __expf(sc[nt][2] - mn1);
            float p3 = __expf(sc[nt][3] - mn1);
            l0 += p0 + p1; l1 += p2 + p3;
            unsigned* pp = prow + nt * 8 + 2 * fc;
            *(uint2*)pp = make_uint2(f2tf32(p0), f2tf32(p1));
            *(uint2*)(pp + 8 * ASTR) = make_uint2(f2tf32(p2), f2tf32(p3));
        }
        mrun0 = mn0; mrun1 = mn1;
        __syncwarp();

        // O += P @ V
        #pragma unroll
        for (int ks = 0; ks < 8; ks++) {
            unsigned a0, a1, a2, a3;
            ldsm4(a0, a1, a2, a3, qAddr + ((ks * 8) << 2));
            #pragma unroll
            for (int ntp = 0; ntp < 4; ntp++) {
                unsigned b0, b1, b2, b3;
                ldsm4(b0, b1, b2, b3, vAddr + ((ntp * 16 * ASTR + ks * 8) << 2));
                mma_tf32(o[2 * ntp + 0], a0, a1, a2, a3, b0, b1);
                mma_tf32(o[2 * ntp + 1], a0, a1, a2, a3, b2, b3);
            }
        }
        __syncwarp();
    }

    l0 += __shfl_xor_sync(0xffffffffu, l0, 1);
    l0 += __shfl_xor_sync(0xffffffffu, l0, 2);
    l1 += __shfl_xor_sync(0xffffffffu, l1, 1);
    l1 += __shfl_xor_sync(0xffffffffu, l1, 2);
    float inv0 = 1.f / l0, inv1 = 1.f / l1;

    int r0 = qt * 64 + w * 16 + fr;
    float* op0 = Op + (size_t)r0 * DMODEL;
    float* op1 = op0 + 8 * DMODEL;
    #pragma unroll
    for (int nt = 0; nt < 8; nt++) {
        int c = nt * 8 + 2 * fc;
        float2 v0; v0.x = rndtf32(o[nt][0] * inv0); v0.y = rndtf32(o[nt][1] * inv0);
        float2 v1; v1.x = rndtf32(o[nt][2] * inv1); v1.y = rndtf32(o[nt][3] * inv1);
        *(float2*)(op0 + c) = v0;
        *(float2*)(op1 + c) = v1;
    }
}

// ---------------- launch ----------------
extern "C" void kernel_launch(void* const* d_in, const int* in_sizes, int n_in,
                              void* d_out, int out_size)
{
    const float* x     = (const float*)d_in[0];
    const float* Wq    = (const float*)d_in[1];
    const float* Wk    = (const float*)d_in[2];
    const float* Wv    = (const float*)d_in[3];
    const float* Wo    = (const float*)d_in[4];
    const float* Wup   = (const float*)d_in[5];
    const float* Wdown = (const float*)d_in[6];
    const float* ln1m  = (const float*)d_in[7];
    const float* ln1s  = (const float*)d_in[8];
    const float* ln2m  = (const float*)d_in[9];
    const float* ln2s  = (const float*)d_in[10];
    float* out = (float*)d_out;

    float *ln, *q, *k, *v, *pre, *x1, *mid;
    float *wq, *wk, *wv, *wo, *wu, *wd;
    cudaGetSymbolAddress((void**)&ln,  g_ln);
    cudaGetSymbolAddress((void**)&q,   g_q);
    cudaGetSymbolAddress((void**)&k,   g_k);
    cudaGetSymbolAddress((void**)&v,   g_v);
    cudaGetSymbolAddress((void**)&pre, g_pre);
    cudaGetSymbolAddress((void**)&x1,  g_x1);
    cudaGetSymbolAddress((void**)&mid, g_mid);
    cudaGetSymbolAddress((void**)&wq,  g_wq);
    cudaGetSymbolAddress((void**)&wk,  g_wk);
    cudaGetSymbolAddress((void**)&wv,  g_wv);
    cudaGetSymbolAddress((void**)&wo,  g_wo);
    cudaGetSymbolAddress((void**)&wu,  g_wu);
    cudaGetSymbolAddress((void**)&wd,  g_wd);

    cudaFuncSetAttribute(gemm_tf32_kernel<0,0>, cudaFuncAttributeMaxDynamicSharedMemorySize, GEMM_SMEM);
    cudaFuncSetAttribute(gemm_tf32_kernel<0,1>, cudaFuncAttributeMaxDynamicSharedMemorySize, GEMM_SMEM);
    cudaFuncSetAttribute(gemm_tf32_kernel<1,1>, cudaFuncAttributeMaxDynamicSharedMemorySize, GEMM_SMEM);
    cudaFuncSetAttribute(attn_mma_kernel,       cudaFuncAttributeMaxDynamicSharedMemorySize, ATT_SMEM);

    // pre-round weights to tf32 (rna)
    const int DD4 = DMODEL * DMODEL / 4, DF4 = DFF * DMODEL / 4;
    round_tf32_kernel<<<(DD4 + 255) / 256, 256>>>((const float4*)Wq, (float4*)wq, DD4);
    round_tf32_kernel<<<(DD4 + 255) / 256, 256>>>((const float4*)Wk, (float4*)wk, DD4);
    round_tf32_kernel<<<(DD4 + 255) / 256, 256>>>((const float4*)Wv, (float4*)wv, DD4);
    round_tf32_kernel<<<(DD4 + 255) / 256, 256>>>((const float4*)Wo, (float4*)wo, DD4);
    round_tf32_kernel<<<(DF4 + 255) / 256, 256>>>((const float4*)Wup, (float4*)wu, DF4);
    round_tf32_kernel<<<(DF4 + 255) / 256, 256>>>((const float4*)Wdown, (float4*)wd, DF4);

    // LN1 (rounded output)
    ln_kernel<<<MTOK, 256>>>(x, ln1m, ln1s, ln);

    // Q, K, V projections (rounded outputs feed attention MMA)
    dim3 gD(DMODEL / 128, MTOK / 128);
    gemm_tf32_kernel<0,1><<<gD, 128, GEMM_SMEM>>>(ln, wq, nullptr, q, MTOK, DMODEL, DMODEL);
    gemm_tf32_kernel<0,1><<<gD, 128, GEMM_SMEM>>>(ln, wk, nullptr, k, MTOK, DMODEL, DMODEL);
    gemm_tf32_kernel<0,1><<<gD, 128, GEMM_SMEM>>>(ln, wv, nullptr, v, MTOK, DMODEL, DMODEL);

    // causal flash attention (tensor cores; rounded output feeds Wo GEMM)
    attn_mma_kernel<<<dim3(SEQ / 64, BATCH * NHEADS), 128, ATT_SMEM>>>(q, k, v, pre);

    // output projection + residual (x1 = x + attn_out; full fp32 out)
    gemm_tf32_kernel<0,0><<<gD, 128, GEMM_SMEM>>>(pre, wo, x, x1, MTOK, DMODEL, DMODEL);

    // LN2 (rounded output)
    ln_kernel<<<MTOK, 256>>>(x1, ln2m, ln2s, ln);

    // MLP up + exact GELU (rounded output feeds down GEMM)
    dim3 gUp(DFF / 128, MTOK / 128);
    gemm_tf32_kernel<1,1><<<gUp, 128, GEMM_SMEM>>>(ln, wu, nullptr, mid, MTOK, DFF, DMODEL);

    // MLP down + residual -> output (full fp32)
    gemm_tf32_kernel<0,0><<<gD, 128, GEMM_SMEM>>>(mid, wd, x1, out, MTOK, DMODEL, DFF);
}

// round 13
// speedup vs baseline: 1.1163x; 1.1163x over previous
#include <cuda_runtime.h>
#include <math.h>

#define DMODEL 1024
#define SEQ    2048
#define BATCH  2
#define NHEADS 16
#define HDIM   64
#define MTOK   (BATCH*SEQ)   // 4096
#define DFF    (4*DMODEL)    // 4096
#define LN_EPS 1e-9f

// ---------------- scratch (device globals: allocation-free) ----------------
__device__ float g_ln [MTOK*DMODEL];
__device__ float g_q  [MTOK*DMODEL];
__device__ float g_k  [MTOK*DMODEL];
__device__ float g_v  [MTOK*DMODEL];
__device__ float g_pre[MTOK*DMODEL];
__device__ float g_x1 [MTOK*DMODEL];
__device__ float g_mid[MTOK*DFF];

// ---------------- helpers ----------------
__device__ __forceinline__ float gelu_exact(float x) {
    return 0.5f * x * (1.f + erff(x * 0.70710678118654752f));
}
__device__ __forceinline__ unsigned f2tf32(float f) {
    unsigned u;
    asm("cvt.rna.tf32.f32 %0, %1;" : "=r"(u) : "f"(f));
    return u;
}
__device__ __forceinline__ float rndtf32(float f) {
    return __uint_as_float(f2tf32(f));
}
__device__ __forceinline__ void mma_tf32(float c[4],
    unsigned a0, unsigned a1, unsigned a2, unsigned a3,
    unsigned b0, unsigned b1)
{
    asm volatile(
        "mma.sync.aligned.m16n8k8.row.col.f32.tf32.tf32.f32 "
        "{%0,%1,%2,%3}, {%4,%5,%6,%7}, {%8,%9}, {%0,%1,%2,%3};\n"
        : "+f"(c[0]), "+f"(c[1]), "+f"(c[2]), "+f"(c[3])
        : "r"(a0), "r"(a1), "r"(a2), "r"(a3), "r"(b0), "r"(b1));
}
__device__ __forceinline__ void ldsm4(unsigned &r0, unsigned &r1,
                                      unsigned &r2, unsigned &r3, unsigned addr)
{
    asm volatile("ldmatrix.sync.aligned.m8n8.x4.shared.b16 {%0,%1,%2,%3}, [%4];"
        : "=r"(r0), "=r"(r1), "=r"(r2), "=r"(r3) : "r"(addr));
}
__device__ __forceinline__ unsigned smem_u32(const void* p) {
    return (unsigned)__cvta_generic_to_shared(p);
}
__device__ __forceinline__ void cpasync16(unsigned dst, const void* src) {
    asm volatile("cp.async.cg.shared.global [%0], [%1], 16;" :: "r"(dst), "l"(src));
}
#define CP_COMMIT asm volatile("cp.async.commit_group;")
#define CP_WAIT0  asm volatile("cp.async.wait_group 0;")
#define CP_WAIT1  asm volatile("cp.async.wait_group 1;")

// ---------------- LayerNorm (ddof=1, eps inside sqrt), tf32-rounded out ----
__global__ void __launch_bounds__(256) ln_kernel(
    const float* __restrict__ x,
    const float* __restrict__ msc,
    const float* __restrict__ ssc,
    float* __restrict__ out)
{
    __shared__ float xs[DMODEL];
    __shared__ float rs[16];
    int row = blockIdx.x;
    const float* xr = x + (size_t)row * DMODEL;
    float s = 0.f, s2 = 0.f;
    #pragma unroll
    for (int i = threadIdx.x; i < DMODEL; i += 256) {
        float v = xr[i]; xs[i] = v; s += v; s2 += v * v;
    }
    #pragma unroll
    for (int o = 16; o > 0; o >>= 1) {
        s  += __shfl_down_sync(0xffffffffu, s,  o);
        s2 += __shfl_down_sync(0xffffffffu, s2, o);
    }
    int wid = threadIdx.x >> 5;
    if ((threadIdx.x & 31) == 0) { rs[wid] = s; rs[8 + wid] = s2; }
    __syncthreads();
    s = 0.f; s2 = 0.f;
    #pragma unroll
    for (int w = 0; w < 8; w++) { s += rs[w]; s2 += rs[8 + w]; }
    float mean = s * (1.f / DMODEL);
    float var  = (s2 - (float)DMODEL * mean * mean) * (1.f / (DMODEL - 1));
    float inv  = rsqrtf(var + LN_EPS);
    float* outr = out + (size_t)row * DMODEL;
    #pragma unroll
    for (int i = threadIdx.x; i < DMODEL; i += 256)
        outr[i] = rndtf32((xs[i] - mean) * inv * ssc[i] + msc[i]);
}

// ---------------- TF32 GEMM  C = A(MxK)*W(NxK)^T [+Res][+GELU], 3-stage ----
// (R6 config: 256 threads, 8 warps of 64x32, occ 2)
#define GBM 128
#define GBN 128
#define GBK 32
#define GBKP 36
#define GABUF (GBM*GBKP)
#define NSTG 3
#define GEMM_SMEM (NSTG*2*GABUF*4)

template<int GELU, int ROUND>
__global__ void __launch_bounds__(256, 2) gemm_tf32_kernel(
    const float* __restrict__ A, const float* __restrict__ W,
    const float* __restrict__ Res, float* __restrict__ C,
    int M, int N, int K)
{
    extern __shared__ unsigned gsm[];
    unsigned* As = gsm;                  // [3][128*36]
    unsigned* Bs = gsm + NSTG * GABUF;   // [3][128*36]

    int bm = blockIdx.y * GBM, bn = blockIdx.x * GBN;
    int tid = threadIdx.x, lane = tid & 31, wid = tid >> 5;
    int m_base = (wid & 1) * 64;
    int n_base = (wid >> 1) * 32;

    int lr = tid >> 1;               // 0..127
    int lk = (tid & 1) * 16;         // 0 or 16
    const float* Ag = A + (size_t)(bm + lr) * K + lk;
    const float* Wg = W + (size_t)(bn + lr) * K + lk;
    unsigned aDst = smem_u32(As) + ((lr * GBKP + lk) << 2);
    unsigned bDst = aDst + NSTG * GABUF * 4;

    unsigned aAddr0 = smem_u32(As) +
        (((m_base + (lane & 15)) * GBKP + ((lane >> 4) << 2)) << 2);
    unsigned bAddr0 = smem_u32(Bs) +
        (((n_base + (lane & 7) + (((lane >> 4) & 1) << 3)) * GBKP + (((lane >> 3) & 1) << 2)) << 2);

    float acc[4][4][4];
    #pragma unroll
    for (int mt = 0; mt < 4; mt++)
        #pragma unroll
        for (int nt = 0; nt < 4; nt++)
            #pragma unroll
            for (int e = 0; e < 4; e++) acc[mt][nt][e] = 0.f;

    int ntiles = K / GBK;

    // prologue: stage tiles 0 and 1
    #pragma unroll
    for (int s = 0; s < 2; s++) {
        int koff = s * GBK;
        unsigned aD = aDst + s * (GABUF * 4);
        unsigned bD = bDst + s * (GABUF * 4);
        #pragma unroll
        for (int i = 0; i < 4; i++) {
            cpasync16(aD + i * 16, Ag + koff + i * 4);
            cpasync16(bD + i * 16, Wg + koff + i * 4);
        }
        CP_COMMIT;
    }

    for (int kb = 0; kb < ntiles; kb++) {
        CP_WAIT1;          // tile kb landed (<=1 group pending)
        __syncthreads();   // visible block-wide; buf (kb+2)%3 reads finished

        if (kb + 2 < ntiles) {           // prefetch kb+2
            int st = (kb + 2) % NSTG;
            int koff = (kb + 2) * GBK;
            unsigned aD = aDst + st * (GABUF * 4);
            unsigned bD = bDst + st * (GABUF * 4);
            #pragma unroll
            for (int i = 0; i < 4; i++) {
                cpasync16(aD + i * 16, Ag + koff + i * 4);
                cpasync16(bD + i * 16, Wg + koff + i * 4);
            }
        }
        CP_COMMIT;

        int cur = kb % NSTG;
        unsigned aC = aAddr0 + cur * (GABUF * 4);
        unsigned bC = bAddr0 + cur * (GABUF * 4);
        #pragma unroll
        for (int ks = 0; ks < 4; ks++) {
            unsigned a[4][4];
            #pragma unroll
            for (int mt = 0; mt < 4; mt++)
                ldsm4(a[mt][0], a[mt][1], a[mt][2], a[mt][3],
                      aC + ((mt * 16 * GBKP + ks * 8) << 2));
            #pragma unroll
            for (int ntp = 0; ntp < 2; ntp++) {
                unsigned b0, b1, b2, b3;
                ldsm4(b0, b1, b2, b3, bC + ((ntp * 16 * GBKP + ks * 8) << 2));
                #pragma unroll
                for (int mt = 0; mt < 4; mt++) {
                    mma_tf32(acc[mt][2 * ntp + 0], a[mt][0], a[mt][1], a[mt][2], a[mt][3], b0, b1);
                    mma_tf32(acc[mt][2 * ntp + 1], a[mt][0], a[mt][1], a[mt][2], a[mt][3], b2, b3);
                }
            }
        }
    }

    int er = lane >> 2, ec = (lane & 3) * 2;
    #pragma unroll
    for (int mt = 0; mt < 4; mt++) {
        #pragma unroll
        for (int nt = 0; nt < 4; nt++) {
            int row = bm + m_base + mt * 16 + er;
            int col = bn + n_base + nt * 8 + ec;
            #pragma unroll
            for (int half = 0; half < 2; half++) {
                int r2 = row + half * 8;
                float2 v;
                v.x = acc[mt][nt][half * 2 + 0];
                v.y = acc[mt][nt][half * 2 + 1];
                if (Res) {
                    float2 rr = *(const float2*)(Res + (size_t)r2 * N + col);
                    v.x += rr.x; v.y += rr.y;
                }
                if (GELU) { v.x = gelu_exact(v.x); v.y = gelu_exact(v.y); }
                if (ROUND) { v.x = rndtf32(v.x); v.y = rndtf32(v.y); }
                *(float2*)(C + (size_t)r2 * N + col) = v;
            }
        }
    }
}

// ---------------- Flash attention: 128-row q-tiles, 256 threads ----------------
#define ASTR 68
#define QT 128
#define ATT_SMEM ((QT+64+64)*ASTR*4)

__global__ void __launch_bounds__(256) attn_mma_kernel(
    const float* __restrict__ Q, const float* __restrict__ K,
    const float* __restrict__ V, float* __restrict__ O)
{
    extern __shared__ unsigned sm[];
    unsigned* Qs = sm;                  // 128*68 (Q, later P per-warp blocks)
    unsigned* Ks = sm + QT * ASTR;      // 64*68
    unsigned* Vs = sm + (QT + 64) * ASTR; // 64*68, [d][key]

    int qt = gridDim.x - 1 - blockIdx.x;   // heavy tiles first
    int bh = blockIdx.y;
    int b = bh >> 4, h = bh & 15;
    int tid = threadIdx.x, lane = tid & 31, w = tid >> 5;   // w 0..7
    int fr = lane >> 2, fc = lane & 3;

    const float* Qp = Q + (size_t)b * SEQ * DMODEL + h * HDIM;
    const float* Kp = K + (size_t)b * SEQ * DMODEL + h * HDIM;
    const float* Vp = V + (size_t)b * SEQ * DMODEL + h * HDIM;
    float*       Op = O + (size_t)b * SEQ * DMODEL + h * HDIM;

    unsigned aSel = ((lane & 15) * ASTR + ((lane >> 4) << 2)) << 2;
    unsigned bSel = (((lane & 7) + (((lane >> 4) & 1) << 3)) * ASTR
                     + (((lane >> 3) & 1) << 2)) << 2;
    unsigned qAddr = smem_u32(Qs) + ((w * 16 * ASTR) << 2) + aSel;
    unsigned kAddr = smem_u32(Ks) + bSel;
    unsigned vAddr = smem_u32(Vs) + bSel;

    // Q load: 128 rows x 64 cols, scaled 1/8 (exact pow2, tf32-safe)
    {
        int ldr = tid >> 1, ldc = (tid & 1) * 32;
        const float* qp = Qp + (size_t)(qt * QT + ldr) * DMODEL + ldc;
        unsigned* qs = Qs + ldr * ASTR + ldc;
        #pragma unroll
        for (int i = 0; i < 8; i++) {
            float4 v = *(const float4*)(qp + i * 4);
            qs[i * 4 + 0] = __float_as_uint(v.x * 0.125f);
            qs[i * 4 + 1] = __float_as_uint(v.y * 0.125f);
            qs[i * 4 + 2] = __float_as_uint(v.z * 0.125f);
            qs[i * 4 + 3] = __float_as_uint(v.w * 0.125f);
        }
    }
    __syncthreads();

    unsigned qa[8][4];
    #pragma unroll
    for (int ks = 0; ks < 8; ks++)
        ldsm4(qa[ks][0], qa[ks][1], qa[ks][2], qa[ks][3], qAddr + ((ks * 8) << 2));

    float o[8][4];
    #pragma unroll
    for (int nt = 0; nt < 8; nt++)
        #pragma unroll
        for (int e = 0; e < 4; e++) o[nt][e] = 0.f;
    float mrun0 = -INFINITY, mrun1 = -INFINITY, l0 = 0.f, l1 = 0.f;

    unsigned* prow = Qs + (w * 16 + fr) * ASTR;
    int kr = tid >> 2, kc = (tid & 3) * 16;
    unsigned kDst = smem_u32(Ks) + ((kr * ASTR + kc) << 2);

    int kmax = 2 * qt + 1;
    for (int kt = 0; kt <= kmax; kt++) {
        __syncthreads();    // prev tile's K/V reads done
        // K tile via cp.async
        {
            const float* kp = Kp + (size_t)(kt * 64 + kr) * DMODEL + kc;
            #pragma unroll
            for (int i = 0; i < 4; i++)
                cpasync16(kDst + i * 16, kp + i * 4);
            CP_COMMIT;
        }
        // V tile transposed: Vs[d][key]
        {
            int key = tid & 63;
            int dh = (tid >> 6) * 16;   // 4 groups of 16 d
            const float* vp = Vp + (size_t)(kt * 64 + key) * DMODEL;
            #pragma unroll
            for (int i = 0; i < 4; i++) {
                int d0 = dh + i * 4;
                float4 v = *(const float4*)(vp + d0);
                Vs[(d0 + 0) * ASTR + key] = __float_as_uint(v.x);
                Vs[(d0 + 1) * ASTR + key] = __float_as_uint(v.y);
                Vs[(d0 + 2) * ASTR + key] = __float_as_uint(v.z);
                Vs[(d0 + 3) * ASTR + key] = __float_as_uint(v.w);
            }
        }
        CP_WAIT0;
        __syncthreads();

        // S = Q @ K^T  (16 q-rows x 64 keys per warp)
        float sc[8][4];
        #pragma unroll
        for (int nt = 0; nt < 8; nt++)
            #pragma unroll
            for (int e = 0; e < 4; e++) sc[nt][e] = 0.f;
        #pragma unroll
        for (int ks = 0; ks < 8; ks++) {
            #pragma unroll
            for (int ntp = 0; ntp < 4; ntp++) {
                unsigned b0, b1, b2, b3;
                ldsm4(b0, b1, b2, b3, kAddr + ((ntp * 16 * ASTR + ks * 8) << 2));
                mma_tf32(sc[2 * ntp + 0], qa[ks][0], qa[ks][1], qa[ks][2], qa[ks][3], b0, b1);
                mma_tf32(sc[2 * ntp + 1], qa[ks][0], qa[ks][1], qa[ks][2], qa[ks][3], b2, b3);
            }
        }

        // causal mask (only possible on the last two k-tiles), global indices
        if (kt >= 2 * qt) {
            int qg0 = qt * QT + w * 16 + fr, qg1 = qg0 + 8;
            int kb0 = kt * 64;
            #pragma unroll
            for (int nt = 0; nt < 8; nt++) {
                int kg = kb0 + nt * 8 + 2 * fc;
                if (kg     > qg0) sc[nt][0] = -INFINITY;
                if (kg + 1 > qg0) sc[nt][1] = -INFINITY;
                if (kg     > qg1) sc[nt][2] = -INFINITY;
                if (kg + 1 > qg1) sc[nt][3] = -INFINITY;
            }
        }

        // online softmax
        float m0 = -INFINITY, m1 = -INFINITY;
        #pragma unroll
        for (int nt = 0; nt < 8; nt++) {
            m0 = fmaxf(m0, fmaxf(sc[nt][0], sc[nt][1]));
            m1 = fmaxf(m1, fmaxf(sc[nt][2], sc[nt][3]));
        }
        m0 = fmaxf(m0, __shfl_xor_sync(0xffffffffu, m0, 1));
        m0 = fmaxf(m0, __shfl_xor_sync(0xffffffffu, m0, 2));
        m1 = fmaxf(m1, __shfl_xor_sync(0xffffffffu, m1, 1));
        m1 = fmaxf(m1, __shfl_xor_sync(0xffffffffu, m1, 2));
        float mn0 = fmaxf(mrun0, m0), mn1 = fmaxf(mrun1, m1);
        float corr0 = __expf(mrun0 - mn0), corr1 = __expf(mrun1 - mn1);
        l0 *= corr0; l1 *= corr1;
        #pragma unroll
        for (int nt = 0; nt < 8; nt++) {
            o[nt][0] *= corr0; o[nt][1] *= corr0;
            o[nt][2] *= corr1; o[nt][3] *= corr1;
        }
        #pragma unroll
        for (int nt = 0; nt < 8; nt++) {
            float p0 = __expf(sc[nt][0] - mn0);
            float p1 = __expf(sc[nt][1] - mn0);
            float p2 = __expf(sc[nt][2] - mn1);
            float p3 = __expf(sc[nt][3] - mn1);
            l0 += p0 + p1; l1 += p2 + p3;
            unsigned* pp = prow + nt * 8 + 2 * fc;
            *(uint2*)pp = make_uint2(f2tf32(p0), f2tf32(p1));
            *(uint2*)(pp + 8 * ASTR) = make_uint2(f2tf32(p2), f2tf32(p3));
        }
        mrun0 = mn0; mrun1 = mn1;
        __syncwarp();

        // O += P @ V  (P warp-local in Qs block)
        #pragma unroll
        for (int ks = 0; ks < 8; ks++) {
            unsigned a0, a1, a2, a3;
            ldsm4(a0, a1, a2, a3, qAddr + ((ks * 8) << 2));
            #pragma unroll
            for (int ntp = 0; ntp < 4; ntp++) {
                unsigned b0, b1, b2, b3;
                ldsm4(b0, b1, b2, b3, vAddr + ((ntp * 16 * ASTR + ks * 8) << 2));
                mma_tf32(o[2 * ntp + 0], a0, a1, a2, a3, b0, b1);
                mma_tf32(o[2 * ntp + 1], a0, a1, a2, a3, b2, b3);
            }
        }
        __syncwarp();   // PV reads done before next tile overwrites P
    }

    l0 += __shfl_xor_sync(0xffffffffu, l0, 1);
    l0 += __shfl_xor_sync(0xffffffffu, l0, 2);
    l1 += __shfl_xor_sync(0xffffffffu, l1, 1);
    l1 += __shfl_xor_sync(0xffffffffu, l1, 2);
    float inv0 = 1.f / l0, inv1 = 1.f / l1;

    int r0 = qt * QT + w * 16 + fr;
    float* op0 = Op + (size_t)r0 * DMODEL;
    float* op1 = op0 + 8 * DMODEL;
    #pragma unroll
    for (int nt = 0; nt < 8; nt++) {
        int c = nt * 8 + 2 * fc;
        float2 v0; v0.x = rndtf32(o[nt][0] * inv0); v0.y = rndtf32(o[nt][1] * inv0);
        float2 v1; v1.x = rndtf32(o[nt][2] * inv1); v1.y = rndtf32(o[nt][3] * inv1);
        *(float2*)(op0 + c) = v0;
        *(float2*)(op1 + c) = v1;
    }
}

// ---------------- launch ----------------
extern "C" void kernel_launch(void* const* d_in, const int* in_sizes, int n_in,
                              void* d_out, int out_size)
{
    const float* x     = (const float*)d_in[0];
    const float* Wq    = (const float*)d_in[1];
    const float* Wk    = (const float*)d_in[2];
    const float* Wv    = (const float*)d_in[3];
    const float* Wo    = (const float*)d_in[4];
    const float* Wup   = (const float*)d_in[5];
    const float* Wdown = (const float*)d_in[6];
    const float* ln1m  = (const float*)d_in[7];
    const float* ln1s  = (const float*)d_in[8];
    const float* ln2m  = (const float*)d_in[9];
    const float* ln2s  = (const float*)d_in[10];
    float* out = (float*)d_out;

    float *ln, *q, *k, *v, *pre, *x1, *mid;
    cudaGetSymbolAddress((void**)&ln,  g_ln);
    cudaGetSymbolAddress((void**)&q,   g_q);
    cudaGetSymbolAddress((void**)&k,   g_k);
    cudaGetSymbolAddress((void**)&v,   g_v);
    cudaGetSymbolAddress((void**)&pre, g_pre);
    cudaGetSymbolAddress((void**)&x1,  g_x1);
    cudaGetSymbolAddress((void**)&mid, g_mid);

    cudaFuncSetAttribute(gemm_tf32_kernel<0,0>, cudaFuncAttributeMaxDynamicSharedMemorySize, GEMM_SMEM);
    cudaFuncSetAttribute(gemm_tf32_kernel<0,1>, cudaFuncAttributeMaxDynamicSharedMemorySize, GEMM_SMEM);
    cudaFuncSetAttribute(gemm_tf32_kernel<1,1>, cudaFuncAttributeMaxDynamicSharedMemorySize, GEMM_SMEM);
    cudaFuncSetAttribute(attn_mma_kernel,       cudaFuncAttributeMaxDynamicSharedMemorySize, ATT_SMEM);

    // LN1 (rounded output)
    ln_kernel<<<MTOK, 256>>>(x, ln1m, ln1s, ln);

    // Q, K, V projections (weights truncated by mma; outputs rna-rounded)
    dim3 gD(DMODEL / 128, MTOK / 128);
    gemm_tf32_kernel<0,1><<<gD, 256, GEMM_SMEM>>>(ln, Wq, nullptr, q, MTOK, DMODEL, DMODEL);
    gemm_tf32_kernel<0,1><<<gD, 256, GEMM_SMEM>>>(ln, Wk, nullptr, k, MTOK, DMODEL, DMODEL);
    gemm_tf32_kernel<0,1><<<gD, 256, GEMM_SMEM>>>(ln, Wv, nullptr, v, MTOK, DMODEL, DMODEL);

    // causal flash attention (128-row q-tiles)
    attn_mma_kernel<<<dim3(SEQ / QT, BATCH * NHEADS), 256, ATT_SMEM>>>(q, k, v, pre);

    // output projection + residual (x1 = x + attn_out; full fp32 out)
    gemm_tf32_kernel<0,0><<<gD, 256, GEMM_SMEM>>>(pre, Wo, x, x1, MTOK, DMODEL, DMODEL);

    // LN2 (rounded output)
    ln_kernel<<<MTOK, 256>>>(x1, ln2m, ln2s, ln);

    // MLP up + exact GELU (rounded output)
    dim3 gUp(DFF / 128, MTOK / 128);
    gemm_tf32_kernel<1,1><<<gUp, 256, GEMM_SMEM>>>(ln, Wup, nullptr, mid, MTOK, DFF, DMODEL);

    // MLP down + residual -> output (full fp32)
    gemm_tf32_kernel<0,0><<<gD, 256, GEMM_SMEM>>>(mid, Wdown, x1, out, MTOK, DMODEL, DFF);
}

// round 15
// speedup vs baseline: 2.4097x; 2.1587x over previous
#include <cuda_runtime.h>
#include <cuda_fp16.h>
#include <math.h>

#define DMODEL 1024
#define SEQ    2048
#define BATCH  2
#define NHEADS 16
#define HDIM   64
#define MTOK   (BATCH*SEQ)   // 4096
#define DFF    (4*DMODEL)    // 4096
#define LN_EPS 1e-9f

// ---------------- scratch (device globals: allocation-free) ----------------
__device__ __half h_ln [MTOK*DMODEL];
__device__ __half h_q  [MTOK*DMODEL];
__device__ __half h_k  [MTOK*DMODEL];
__device__ __half h_v  [MTOK*DMODEL];
__device__ __half h_pre[MTOK*DMODEL];
__device__ __half h_mid[MTOK*DFF];
__device__ float  g_x1 [MTOK*DMODEL];
// fp16 weights
__device__ __half h_wq[DMODEL*DMODEL];
__device__ __half h_wk[DMODEL*DMODEL];
__device__ __half h_wv[DMODEL*DMODEL];
__device__ __half h_wo[DMODEL*DMODEL];
__device__ __half h_wu[DFF*DMODEL];
__device__ __half h_wd[DMODEL*DFF];

// ---------------- helpers ----------------
__device__ __forceinline__ float gelu_exact(float x) {
    return 0.5f * x * (1.f + erff(x * 0.70710678118654752f));
}
__device__ __forceinline__ void mma_f16(float c[4],
    unsigned a0, unsigned a1, unsigned a2, unsigned a3,
    unsigned b0, unsigned b1)
{
    asm volatile(
        "mma.sync.aligned.m16n8k16.row.col.f32.f16.f16.f32 "
        "{%0,%1,%2,%3}, {%4,%5,%6,%7}, {%8,%9}, {%0,%1,%2,%3};\n"
        : "+f"(c[0]), "+f"(c[1]), "+f"(c[2]), "+f"(c[3])
        : "r"(a0), "r"(a1), "r"(a2), "r"(a3), "r"(b0), "r"(b1));
}
__device__ __forceinline__ void ldsm4(unsigned &r0, unsigned &r1,
                                      unsigned &r2, unsigned &r3, unsigned addr)
{
    asm volatile("ldmatrix.sync.aligned.m8n8.x4.shared.b16 {%0,%1,%2,%3}, [%4];"
        : "=r"(r0), "=r"(r1), "=r"(r2), "=r"(r3) : "r"(addr));
}
__device__ __forceinline__ void ldsm4t(unsigned &r0, unsigned &r1,
                                       unsigned &r2, unsigned &r3, unsigned addr)
{
    asm volatile("ldmatrix.sync.aligned.m8n8.x4.trans.shared.b16 {%0,%1,%2,%3}, [%4];"
        : "=r"(r0), "=r"(r1), "=r"(r2), "=r"(r3) : "r"(addr));
}
__device__ __forceinline__ unsigned smem_u32(const void* p) {
    return (unsigned)__cvta_generic_to_shared(p);
}
__device__ __forceinline__ void cpasync16(unsigned dst, const void* src) {
    asm volatile("cp.async.cg.shared.global [%0], [%1], 16;" :: "r"(dst), "l"(src));
}
#define CP_COMMIT asm volatile("cp.async.commit_group;")
#define CP_WAIT0  asm volatile("cp.async.wait_group 0;")
#define CP_WAIT1  asm volatile("cp.async.wait_group 1;")

__device__ __forceinline__ void store2(__half* p, float x, float y) {
    __half2 h = __floats2half2_rn(x, y);
    *(unsigned*)p = *(unsigned*)&h;
}
__device__ __forceinline__ void store2(float* p, float x, float y) {
    float2 v; v.x = x; v.y = y;
    *(float2*)p = v;
}
__device__ __forceinline__ unsigned packh2(float lo, float hi) {
    __half2 h = __floats2half2_rn(lo, hi);
    return *(unsigned*)&h;
}

// ---------------- fp32 -> fp16 weight conversion ----------------
__global__ void __launch_bounds__(256) f32_to_f16_kernel(
    const float4* __restrict__ src, uint4* __restrict__ dst, int n8)
{
    int i = blockIdx.x * 256 + threadIdx.x;
    if (i < n8) {
        float4 a = src[2 * i], b = src[2 * i + 1];
        uint4 o;
        o.x = packh2(a.x, a.y); o.y = packh2(a.z, a.w);
        o.z = packh2(b.x, b.y); o.w = packh2(b.z, b.w);
        dst[i] = o;
    }
}

// ---------------- LayerNorm (ddof=1, eps inside sqrt), fp16 out ----------
__global__ void __launch_bounds__(256) ln_kernel(
    const float* __restrict__ x,
    const float* __restrict__ msc,
    const float* __restrict__ ssc,
    __half* __restrict__ out)
{
    __shared__ float xs[DMODEL];
    __shared__ float rs[16];
    int row = blockIdx.x;
    const float* xr = x + (size_t)row * DMODEL;
    float s = 0.f, s2 = 0.f;
    #pragma unroll
    for (int i = threadIdx.x; i < DMODEL; i += 256) {
        float v = xr[i]; xs[i] = v; s += v; s2 += v * v;
    }
    #pragma unroll
    for (int o = 16; o > 0; o >>= 1) {
        s  += __shfl_down_sync(0xffffffffu, s,  o);
        s2 += __shfl_down_sync(0xffffffffu, s2, o);
    }
    int wid = threadIdx.x >> 5;
    if ((threadIdx.x & 31) == 0) { rs[wid] = s; rs[8 + wid] = s2; }
    __syncthreads();
    s = 0.f; s2 = 0.f;
    #pragma unroll
    for (int w = 0; w < 8; w++) { s += rs[w]; s2 += rs[8 + w]; }
    float mean = s * (1.f / DMODEL);
    float var  = (s2 - (float)DMODEL * mean * mean) * (1.f / (DMODEL - 1));
    float inv  = rsqrtf(var + LN_EPS);
    __half* outr = out + (size_t)row * DMODEL;
    #pragma unroll
    for (int i = threadIdx.x; i < DMODEL; i += 256)
        outr[i] = __float2half_rn((xs[i] - mean) * inv * ssc[i] + msc[i]);
}

// ---------------- FP16 GEMM  C = A(MxK)*W(NxK)^T [+Res][+GELU], 3-stage ----
// 128x128 CTA tile, 8 warps of 64x32, m16n8k16, smem row stride 80B.
#define GBK 32                     // halves per k-tile
#define GROWB 80                   // bytes per smem row (32 halves + pad)
#define GTILE 10240                // 128 rows * 80 B
#define GSTAGE (2*GTILE)           // A + B
#define NSTG 3
#define GEMM_SMEM (NSTG*GSTAGE)

template<int GELU, typename OUT>
__global__ void __launch_bounds__(256, 2) gemm_f16_kernel(
    const __half* __restrict__ A, const __half* __restrict__ W,
    const float* __restrict__ Res, OUT* __restrict__ C,
    int M, int N, int K, float scale)
{
    extern __shared__ char gsm[];
    unsigned sb = smem_u32(gsm);

    int bm = blockIdx.y * 128, bn = blockIdx.x * 128;
    int tid = threadIdx.x, lane = tid & 31, wid = tid >> 5;
    int m_base = (wid & 1) * 64;
    int n_base = (wid >> 1) * 32;

    unsigned aAddr0 = sb + (m_base + (lane & 15)) * GROWB + ((lane >> 4) << 4);
    unsigned bAddr0 = sb + GTILE +
        (n_base + (lane & 7) + (((lane >> 4) & 1) << 3)) * GROWB + (((lane >> 3) & 1) << 4);

    float acc[4][4][4];
    #pragma unroll
    for (int mt = 0; mt < 4; mt++)
        #pragma unroll
        for (int nt = 0; nt < 4; nt++)
            #pragma unroll
            for (int e = 0; e < 4; e++) acc[mt][nt][e] = 0.f;

    int ntiles = K / GBK;

    auto stage_tile = [&](int kb, int st) {
        unsigned base = sb + st * GSTAGE;
        #pragma unroll
        for (int i = 0; i < 2; i++) {
            int c = i * 256 + tid;       // 0..511
            int row = c >> 2, kc = c & 3;
            cpasync16(base + row * GROWB + kc * 16,
                      A + (size_t)(bm + row) * K + kb * GBK + kc * 8);
            cpasync16(base + GTILE + row * GROWB + kc * 16,
                      W + (size_t)(bn + row) * K + kb * GBK + kc * 8);
        }
    };

    stage_tile(0, 0); CP_COMMIT;
    if (ntiles > 1) stage_tile(1, 1);
    CP_COMMIT;

    for (int kb = 0; kb < ntiles; kb++) {
        CP_WAIT1;
        __syncthreads();

        if (kb + 2 < ntiles) stage_tile(kb + 2, (kb + 2) % NSTG);
        CP_COMMIT;

        int cur = kb % NSTG;
        unsigned aC = aAddr0 + cur * GSTAGE;
        unsigned bC = bAddr0 + cur * GSTAGE;
        #pragma unroll
        for (int ks = 0; ks < 2; ks++) {
            unsigned a[4][4];
            #pragma unroll
            for (int mt = 0; mt < 4; mt++)
                ldsm4(a[mt][0], a[mt][1], a[mt][2], a[mt][3],
                      aC + mt * 16 * GROWB + ks * 32);
            #pragma unroll
            for (int ntp = 0; ntp < 2; ntp++) {
                unsigned b0, b1, b2, b3;
                ldsm4(b0, b1, b2, b3, bC + ntp * 16 * GROWB + ks * 32);
                #pragma unroll
                for (int mt = 0; mt < 4; mt++) {
                    mma_f16(acc[mt][2 * ntp + 0], a[mt][0], a[mt][1], a[mt][2], a[mt][3], b0, b1);
                    mma_f16(acc[mt][2 * ntp + 1], a[mt][0], a[mt][1], a[mt][2], a[mt][3], b2, b3);
                }
            }
        }
    }

    int er = lane >> 2, ec = (lane & 3) * 2;
    #pragma unroll
    for (int mt = 0; mt < 4; mt++) {
        #pragma unroll
        for (int nt = 0; nt < 4; nt++) {
            int row = bm + m_base + mt * 16 + er;
            int col = bn + n_base + nt * 8 + ec;
            #pragma unroll
            for (int half = 0; half < 2; half++) {
                int r2 = row + half * 8;
                float vx = acc[mt][nt][half * 2 + 0];
                float vy = acc[mt][nt][half * 2 + 1];
                if (Res) {
                    float2 rr = *(const float2*)(Res + (size_t)r2 * N + col);
                    vx += rr.x; vy += rr.y;
                }
                if (GELU) { vx = gelu_exact(vx); vy = gelu_exact(vy); }
                store2(C + (size_t)r2 * N + col, vx * scale, vy * scale);
            }
        }
    }
}

// ---------------- Flash attention, fp16 MMA, 128-row q-tiles, 256 threads ----
#define AROWB 144                  // bytes per smem row (64 halves + pad)
#define QT 128
#define ATT_SMEM ((QT + 64 + 64) * AROWB)

__global__ void __launch_bounds__(256) attn_mma_kernel(
    const __half* __restrict__ Q, const __half* __restrict__ K,
    const __half* __restrict__ V, __half* __restrict__ O)
{
    extern __shared__ char asm_[];
    unsigned sb = smem_u32(asm_);
    unsigned qBase = sb;                       // 128 rows (Q, later P)
    unsigned kBase = sb + QT * AROWB;          // 64 rows
    unsigned vBase = kBase + 64 * AROWB;       // 64 rows [key][d]

    int qt = gridDim.x - 1 - blockIdx.x;       // heavy tiles first
    int bh = blockIdx.y;
    int b = bh >> 4, h = bh & 15;
    int tid = threadIdx.x, lane = tid & 31, w = tid >> 5;   // w 0..7
    int fr = lane >> 2, fc = lane & 3;

    const __half* Qp = Q + (size_t)b * SEQ * DMODEL + h * HDIM;
    const __half* Kp = K + (size_t)b * SEQ * DMODEL + h * HDIM;
    const __half* Vp = V + (size_t)b * SEQ * DMODEL + h * HDIM;
    __half*       Op = O + (size_t)b * SEQ * DMODEL + h * HDIM;

    // fragment addresses
    unsigned qAddr = qBase + (w * 16 + (lane & 15)) * AROWB + ((lane >> 4) << 4); // A pat (Q and P)
    unsigned kAddr = kBase + ((lane & 7) + (((lane >> 4) & 1) << 3)) * AROWB
                           + (((lane >> 3) & 1) << 4);                            // B pat
    unsigned vAddr = vBase + (lane & 15) * AROWB + ((lane >> 4) << 4);            // B-trans pat

    // stage Q tile (128 rows x 128B)
    #pragma unroll
    for (int i = 0; i < 4; i++) {
        int c = i * 256 + tid;
        int row = c >> 3, kc = c & 7;
        cpasync16(qBase + row * AROWB + kc * 16,
                  Qp + (size_t)(qt * QT + row) * DMODEL + kc * 8);
    }
    CP_COMMIT; CP_WAIT0;
    __syncthreads();

    unsigned qa[4][4];
    #pragma unroll
    for (int ks = 0; ks < 4; ks++)
        ldsm4(qa[ks][0], qa[ks][1], qa[ks][2], qa[ks][3], qAddr + ks * 32);

    float o[8][4];
    #pragma unroll
    for (int nt = 0; nt < 8; nt++)
        #pragma unroll
        for (int e = 0; e < 4; e++) o[nt][e] = 0.f;
    float mrun0 = -INFINITY, mrun1 = -INFINITY, l0 = 0.f, l1 = 0.f;

    __half* prow = (__half*)(asm_) + (w * 16 + fr) * (AROWB / 2);

    int kmax = 2 * qt + 1;
    for (int kt = 0; kt <= kmax; kt++) {
        __syncthreads();    // prev tile's smem reads done
        #pragma unroll
        for (int i = 0; i < 2; i++) {
            int c = i * 256 + tid;
            int row = c >> 3, kc = c & 7;
            cpasync16(kBase + row * AROWB + kc * 16,
                      Kp + (size_t)(kt * 64 + row) * DMODEL + kc * 8);
            cpasync16(vBase + row * AROWB + kc * 16,
                      Vp + (size_t)(kt * 64 + row) * DMODEL + kc * 8);
        }
        CP_COMMIT; CP_WAIT0;
        __syncthreads();

        // S = Q @ K^T  (16 q-rows x 64 keys per warp)
        float sc[8][4];
        #pragma unroll
        for (int nt = 0; nt < 8; nt++)
            #pragma unroll
            for (int e = 0; e < 4; e++) sc[nt][e] = 0.f;
        #pragma unroll
        for (int ks = 0; ks < 4; ks++) {
            #pragma unroll
            for (int ntp = 0; ntp < 4; ntp++) {
                unsigned b0, b1, b2, b3;
                ldsm4(b0, b1, b2, b3, kAddr + ntp * 16 * AROWB + ks * 32);
                mma_f16(sc[2 * ntp + 0], qa[ks][0], qa[ks][1], qa[ks][2], qa[ks][3], b0, b1);
                mma_f16(sc[2 * ntp + 1], qa[ks][0], qa[ks][1], qa[ks][2], qa[ks][3], b2, b3);
            }
        }

        // causal mask (only last two k-tiles can clip), global indices
        if (kt >= 2 * qt) {
            int qg0 = qt * QT + w * 16 + fr, qg1 = qg0 + 8;
            int kb0 = kt * 64;
            #pragma unroll
            for (int nt = 0; nt < 8; nt++) {
                int kg = kb0 + nt * 8 + 2 * fc;
                if (kg     > qg0) sc[nt][0] = -INFINITY;
                if (kg + 1 > qg0) sc[nt][1] = -INFINITY;
                if (kg     > qg1) sc[nt][2] = -INFINITY;
                if (kg + 1 > qg1) sc[nt][3] = -INFINITY;
            }
        }

        // online softmax
        float m0 = -INFINITY, m1 = -INFINITY;
        #pragma unroll
        for (int nt = 0; nt < 8; nt++) {
            m0 = fmaxf(m0, fmaxf(sc[nt][0], sc[nt][1]));
            m1 = fmaxf(m1, fmaxf(sc[nt][2], sc[nt][3]));
        }
        m0 = fmaxf(m0, __shfl_xor_sync(0xffffffffu, m0, 1));
        m0 = fmaxf(m0, __shfl_xor_sync(0xffffffffu, m0, 2));
        m1 = fmaxf(m1, __shfl_xor_sync(0xffffffffu, m1, 1));
        m1 = fmaxf(m1, __shfl_xor_sync(0xffffffffu, m1, 2));
        float mn0 = fmaxf(mrun0, m0), mn1 = fmaxf(mrun1, m1);
        float corr0 = __expf(mrun0 - mn0), corr1 = __expf(mrun1 - mn1);
        l0 *= corr0; l1 *= corr1;
        #pragma unroll
        for (int nt = 0; nt < 8; nt++) {
            o[nt][0] *= corr0; o[nt][1] *= corr0;
            o[nt][2] *= corr1; o[nt][3] *= corr1;
        }
        #pragma unroll
        for (int nt = 0; nt < 8; nt++) {
            float p0 = __expf(sc[nt][0] - mn0);
            float p1 = __expf(sc[nt][1] - mn0);
            float p2 = __expf(sc[nt][2] - mn1);
            float p3 = __expf(sc[nt][3] - mn1);
            l0 += p0 + p1; l1 += p2 + p3;
            __half* pp = prow + nt * 8 + 2 * fc;
            *(unsigned*)pp = packh2(p0, p1);
            *(unsigned*)(pp + 8 * (AROWB / 2)) = packh2(p2, p3);
        }
        mrun0 = mn0; mrun1 = mn1;
        __syncwarp();

        // O += P @ V  (P warp-local in Q block; V via ldmatrix.trans)
        #pragma unroll
        for (int ks = 0; ks < 4; ks++) {
            unsigned a0, a1, a2, a3;
            ldsm4(a0, a1, a2, a3, qAddr + ks * 32);
            #pragma unroll
            for (int ntp = 0; ntp < 4; ntp++) {
                unsigned b0, b1, b2, b3;
                ldsm4t(b0, b1, b2, b3, vAddr + ks * 16 * AROWB + ntp * 32);
                mma_f16(o[2 * ntp + 0], a0, a1, a2, a3, b0, b1);
                mma_f16(o[2 * ntp + 1], a0, a1, a2, a3, b2, b3);
            }
        }
        __syncwarp();   // PV reads done before next tile overwrites P
    }

    l0 += __shfl_xor_sync(0xffffffffu, l0, 1);
    l0 += __shfl_xor_sync(0xffffffffu, l0, 2);
    l1 += __shfl_xor_sync(0xffffffffu, l1, 1);
    l1 += __shfl_xor_sync(0xffffffffu, l1, 2);
    float inv0 = 1.f / l0, inv1 = 1.f / l1;

    int r0 = qt * QT + w * 16 + fr;
    __half* op0 = Op + (size_t)r0 * DMODEL;
    __half* op1 = op0 + 8 * DMODEL;
    #pragma unroll
    for (int nt = 0; nt < 8; nt++) {
        int c = nt * 8 + 2 * fc;
        *(unsigned*)(op0 + c) = packh2(o[nt][0] * inv0, o[nt][1] * inv0);
        *(unsigned*)(op1 + c) = packh2(o[nt][2] * inv1, o[nt][3] * inv1);
    }
}

// ---------------- launch ----------------
extern "C" void kernel_launch(void* const* d_in, const int* in_sizes, int n_in,
                              void* d_out, int out_size)
{
    const float* x     = (const float*)d_in[0];
    const float* Wq    = (const float*)d_in[1];
    const float* Wk    = (const float*)d_in[2];
    const float* Wv    = (const float*)d_in[3];
    const float* Wo    = (const float*)d_in[4];
    const float* Wup   = (const float*)d_in[5];
    const float* Wdown = (const float*)d_in[6];
    const float* ln1m  = (const float*)d_in[7];
    const float* ln1s  = (const float*)d_in[8];
    const float* ln2m  = (const float*)d_in[9];
    const float* ln2s  = (const float*)d_in[10];
    float* out = (float*)d_out;

    __half *ln, *q, *k, *v, *pre, *mid;
    __half *wq, *wk, *wv, *wo, *wu, *wd;
    float *x1;
    cudaGetSymbolAddress((void**)&ln,  h_ln);
    cudaGetSymbolAddress((void**)&q,   h_q);
    cudaGetSymbolAddress((void**)&k,   h_k);
    cudaGetSymbolAddress((void**)&v,   h_v);
    cudaGetSymbolAddress((void**)&pre, h_pre);
    cudaGetSymbolAddress((void**)&mid, h_mid);
    cudaGetSymbolAddress((void**)&x1,  g_x1);
    cudaGetSymbolAddress((void**)&wq,  h_wq);
    cudaGetSymbolAddress((void**)&wk,  h_wk);
    cudaGetSymbolAddress((void**)&wv,  h_wv);
    cudaGetSymbolAddress((void**)&wo,  h_wo);
    cudaGetSymbolAddress((void**)&wu,  h_wu);
    cudaGetSymbolAddress((void**)&wd,  h_wd);

    cudaFuncSetAttribute(gemm_f16_kernel<0,__half>, cudaFuncAttributeMaxDynamicSharedMemorySize, GEMM_SMEM);
    cudaFuncSetAttribute(gemm_f16_kernel<1,__half>, cudaFuncAttributeMaxDynamicSharedMemorySize, GEMM_SMEM);
    cudaFuncSetAttribute(gemm_f16_kernel<0,float>,  cudaFuncAttributeMaxDynamicSharedMemorySize, GEMM_SMEM);
    cudaFuncSetAttribute(attn_mma_kernel,           cudaFuncAttributeMaxDynamicSharedMemorySize, ATT_SMEM);

    // convert weights to fp16 (once per launch)
    const int DD8 = DMODEL * DMODEL / 8, DF8 = DFF * DMODEL / 8;
    f32_to_f16_kernel<<<(DD8 + 255) / 256, 256>>>((const float4*)Wq, (uint4*)wq, DD8);
    f32_to_f16_kernel<<<(DD8 + 255) / 256, 256>>>((const float4*)Wk, (uint4*)wk, DD8);
    f32_to_f16_kernel<<<(DD8 + 255) / 256, 256>>>((const float4*)Wv, (uint4*)wv, DD8);
    f32_to_f16_kernel<<<(DD8 + 255) / 256, 256>>>((const float4*)Wo, (uint4*)wo, DD8);
    f32_to_f16_kernel<<<(DF8 + 255) / 256, 256>>>((const float4*)Wup, (uint4*)wu, DF8);
    f32_to_f16_kernel<<<(DF8 + 255) / 256, 256>>>((const float4*)Wdown, (uint4*)wd, DF8);

    // LN1 -> fp16
    ln_kernel<<<MTOK, 256>>>(x, ln1m, ln1s, ln);

    // Q (x 1/sqrt(hd) folded), K, V projections -> fp16
    dim3 gD(DMODEL / 128, MTOK / 128);
    gemm_f16_kernel<0,__half><<<gD, 256, GEMM_SMEM>>>(ln, wq, nullptr, q, MTOK, DMODEL, DMODEL, 0.125f);
    gemm_f16_kernel<0,__half><<<gD, 256, GEMM_SMEM>>>(ln, wk, nullptr, k, MTOK, DMODEL, DMODEL, 1.f);
    gemm_f16_kernel<0,__half><<<gD, 256, GEMM_SMEM>>>(ln, wv, nullptr, v, MTOK, DMODEL, DMODEL, 1.f);

    // causal flash attention -> fp16
    attn_mma_kernel<<<dim3(SEQ / QT, BATCH * NHEADS), 256, ATT_SMEM>>>(q, k, v, pre);

    // output projection + residual -> fp32 x1
    gemm_f16_kernel<0,float><<<gD, 256, GEMM_SMEM>>>(pre, wo, x, x1, MTOK, DMODEL, DMODEL, 1.f);

    // LN2 -> fp16
    ln_kernel<<<MTOK, 256>>>(x1, ln2m, ln2s, ln);

    // MLP up + exact GELU -> fp16
    dim3 gUp(DFF / 128, MTOK / 128);
    gemm_f16_kernel<1,__half><<<gUp, 256, GEMM_SMEM>>>(ln, wu, nullptr, mid, MTOK, DFF, DMODEL, 1.f);

    // MLP down + residual -> fp32 output
    gemm_f16_kernel<0,float><<<gD, 256, GEMM_SMEM>>>(mid, wd, x1, out, MTOK, DMODEL, DFF, 1.f);
}

// round 16
// speedup vs baseline: 2.6414x; 1.0961x over previous
#include <cuda_runtime.h>
#include <cuda_fp16.h>
#include <math.h>

#define DMODEL 1024
#define SEQ    2048
#define BATCH  2
#define NHEADS 16
#define HDIM   64
#define MTOK   (BATCH*SEQ)   // 4096
#define DFF    (4*DMODEL)    // 4096
#define LN_EPS 1e-9f

// ---------------- scratch (device globals: allocation-free) ----------------
__device__ __half h_ln [MTOK*DMODEL];
__device__ __half h_q  [MTOK*DMODEL];
__device__ __half h_k  [MTOK*DMODEL];
__device__ __half h_v  [MTOK*DMODEL];
__device__ __half h_pre[MTOK*DMODEL];
__device__ __half h_mid[MTOK*DFF];
__device__ float  g_x1 [MTOK*DMODEL];
// fp16 weights
__device__ __half h_wq[DMODEL*DMODEL];
__device__ __half h_wk[DMODEL*DMODEL];
__device__ __half h_wv[DMODEL*DMODEL];
__device__ __half h_wo[DMODEL*DMODEL];
__device__ __half h_wu[DFF*DMODEL];
__device__ __half h_wd[DMODEL*DFF];

// ---------------- helpers ----------------
__device__ __forceinline__ float gelu_exact(float x) {
    return 0.5f * x * (1.f + erff(x * 0.70710678118654752f));
}
__device__ __forceinline__ void mma_f16(float c[4],
    unsigned a0, unsigned a1, unsigned a2, unsigned a3,
    unsigned b0, unsigned b1)
{
    asm volatile(
        "mma.sync.aligned.m16n8k16.row.col.f32.f16.f16.f32 "
        "{%0,%1,%2,%3}, {%4,%5,%6,%7}, {%8,%9}, {%0,%1,%2,%3};\n"
        : "+f"(c[0]), "+f"(c[1]), "+f"(c[2]), "+f"(c[3])
        : "r"(a0), "r"(a1), "r"(a2), "r"(a3), "r"(b0), "r"(b1));
}
__device__ __forceinline__ void ldsm4(unsigned &r0, unsigned &r1,
                                      unsigned &r2, unsigned &r3, unsigned addr)
{
    asm volatile("ldmatrix.sync.aligned.m8n8.x4.shared.b16 {%0,%1,%2,%3}, [%4];"
        : "=r"(r0), "=r"(r1), "=r"(r2), "=r"(r3) : "r"(addr));
}
__device__ __forceinline__ void ldsm4t(unsigned &r0, unsigned &r1,
                                       unsigned &r2, unsigned &r3, unsigned addr)
{
    asm volatile("ldmatrix.sync.aligned.m8n8.x4.trans.shared.b16 {%0,%1,%2,%3}, [%4];"
        : "=r"(r0), "=r"(r1), "=r"(r2), "=r"(r3) : "r"(addr));
}
__device__ __forceinline__ unsigned smem_u32(const void* p) {
    return (unsigned)__cvta_generic_to_shared(p);
}
__device__ __forceinline__ void cpasync16(unsigned dst, const void* src) {
    asm volatile("cp.async.cg.shared.global [%0], [%1], 16;" :: "r"(dst), "l"(src));
}
#define CP_COMMIT asm volatile("cp.async.commit_group;")
#define CP_WAIT0  asm volatile("cp.async.wait_group 0;")
#define CP_WAIT1  asm volatile("cp.async.wait_group 1;")

__device__ __forceinline__ void store2(__half* p, float x, float y) {
    __half2 h = __floats2half2_rn(x, y);
    *(unsigned*)p = *(unsigned*)&h;
}
__device__ __forceinline__ void store2(float* p, float x, float y) {
    float2 v; v.x = x; v.y = y;
    *(float2*)p = v;
}
__device__ __forceinline__ unsigned packh2(float lo, float hi) {
    __half2 h = __floats2half2_rn(lo, hi);
    return *(unsigned*)&h;
}

// ---------------- fp32 -> fp16 weight conversion (batched, grid.y picks) ----
__global__ void __launch_bounds__(256) f32_to_f16_multi(
    const float4* s0, const float4* s1, const float4* s2, const float4* s3,
    uint4* d0, uint4* d1, uint4* d2, uint4* d3, int n8)
{
    int i = blockIdx.x * 256 + threadIdx.x;
    if (i >= n8) return;
    const float4* s; uint4* d;
    switch (blockIdx.y) {
        case 0: s = s0; d = d0; break;
        case 1: s = s1; d = d1; break;
        case 2: s = s2; d = d2; break;
        default: s = s3; d = d3; break;
    }
    float4 a = s[2 * i], b = s[2 * i + 1];
    uint4 o;
    o.x = packh2(a.x, a.y); o.y = packh2(a.z, a.w);
    o.z = packh2(b.x, b.y); o.w = packh2(b.z, b.w);
    d[i] = o;
}

// ---------------- LayerNorm (ddof=1, eps inside sqrt), fp16 out ----------
__global__ void __launch_bounds__(256) ln_kernel(
    const float* __restrict__ x,
    const float* __restrict__ msc,
    const float* __restrict__ ssc,
    __half* __restrict__ out)
{
    __shared__ float xs[DMODEL];
    __shared__ float rs[16];
    int row = blockIdx.x;
    const float* xr = x + (size_t)row * DMODEL;
    float s = 0.f, s2 = 0.f;
    #pragma unroll
    for (int i = threadIdx.x; i < DMODEL; i += 256) {
        float v = xr[i]; xs[i] = v; s += v; s2 += v * v;
    }
    #pragma unroll
    for (int o = 16; o > 0; o >>= 1) {
        s  += __shfl_down_sync(0xffffffffu, s,  o);
        s2 += __shfl_down_sync(0xffffffffu, s2, o);
    }
    int wid = threadIdx.x >> 5;
    if ((threadIdx.x & 31) == 0) { rs[wid] = s; rs[8 + wid] = s2; }
    __syncthreads();
    s = 0.f; s2 = 0.f;
    #pragma unroll
    for (int w = 0; w < 8; w++) { s += rs[w]; s2 += rs[8 + w]; }
    float mean = s * (1.f / DMODEL);
    float var  = (s2 - (float)DMODEL * mean * mean) * (1.f / (DMODEL - 1));
    float inv  = rsqrtf(var + LN_EPS);
    __half* outr = out + (size_t)row * DMODEL;
    #pragma unroll
    for (int i = threadIdx.x; i < DMODEL; i += 256)
        outr[i] = __float2half_rn((xs[i] - mean) * inv * ssc[i] + msc[i]);
}

// ---------------- FP16 GEMM  C = A(MxK)*W(NxK)^T [+Res][+GELU], 3-stage ----
// 128x128 CTA tile, 8 warps of 64x32, m16n8k16, k-tile 64 halves, 144B rows.
#define GBK 64                     // halves per k-tile
#define GROWB 144                  // bytes per smem row (64 halves + pad)
#define GTILE (128*GROWB)          // 18432
#define GSTAGE (2*GTILE)           // A + B
#define NSTG 3
#define GEMM_SMEM (NSTG*GSTAGE)

template<int GELU, typename OUT>
__global__ void __launch_bounds__(256, 2) gemm_f16_kernel(
    const __half* __restrict__ A, const __half* __restrict__ W,
    const float* __restrict__ Res, OUT* __restrict__ C,
    int M, int N, int K, float scale)
{
    extern __shared__ char gsm[];
    unsigned sb = smem_u32(gsm);

    int bm = blockIdx.y * 128, bn = blockIdx.x * 128;
    int tid = threadIdx.x, lane = tid & 31, wid = tid >> 5;
    int m_base = (wid & 1) * 64;
    int n_base = (wid >> 1) * 32;

    unsigned aAddr0 = sb + (m_base + (lane & 15)) * GROWB + ((lane >> 4) << 4);
    unsigned bAddr0 = sb + GTILE +
        (n_base + (lane & 7) + (((lane >> 4) & 1) << 3)) * GROWB + (((lane >> 3) & 1) << 4);

    float acc[4][4][4];
    #pragma unroll
    for (int mt = 0; mt < 4; mt++)
        #pragma unroll
        for (int nt = 0; nt < 4; nt++)
            #pragma unroll
            for (int e = 0; e < 4; e++) acc[mt][nt][e] = 0.f;

    int ntiles = K / GBK;

    auto stage_tile = [&](int kb, int st) {
        unsigned base = sb + st * GSTAGE;
        #pragma unroll
        for (int i = 0; i < 4; i++) {
            int c = i * 256 + tid;       // 0..1023
            int row = c >> 3, kc = c & 7;
            cpasync16(base + row * GROWB + kc * 16,
                      A + (size_t)(bm + row) * K + kb * GBK + kc * 8);
            cpasync16(base + GTILE + row * GROWB + kc * 16,
                      W + (size_t)(bn + row) * K + kb * GBK + kc * 8);
        }
    };

    stage_tile(0, 0); CP_COMMIT;
    if (ntiles > 1) stage_tile(1, 1);
    CP_COMMIT;

    for (int kb = 0; kb < ntiles; kb++) {
        CP_WAIT1;
        __syncthreads();

        if (kb + 2 < ntiles) stage_tile(kb + 2, (kb + 2) % NSTG);
        CP_COMMIT;

        int cur = kb % NSTG;
        unsigned aC = aAddr0 + cur * GSTAGE;
        unsigned bC = bAddr0 + cur * GSTAGE;
        #pragma unroll
        for (int ks = 0; ks < 4; ks++) {
            unsigned a[4][4];
            #pragma unroll
            for (int mt = 0; mt < 4; mt++)
                ldsm4(a[mt][0], a[mt][1], a[mt][2], a[mt][3],
                      aC + mt * 16 * GROWB + ks * 32);
            #pragma unroll
            for (int ntp = 0; ntp < 2; ntp++) {
                unsigned b0, b1, b2, b3;
                ldsm4(b0, b1, b2, b3, bC + ntp * 16 * GROWB + ks * 32);
                #pragma unroll
                for (int mt = 0; mt < 4; mt++) {
                    mma_f16(acc[mt][2 * ntp + 0], a[mt][0], a[mt][1], a[mt][2], a[mt][3], b0, b1);
                    mma_f16(acc[mt][2 * ntp + 1], a[mt][0], a[mt][1], a[mt][2], a[mt][3], b2, b3);
                }
            }
        }
    }

    int er = lane >> 2, ec = (lane & 3) * 2;
    #pragma unroll
    for (int mt = 0; mt < 4; mt++) {
        #pragma unroll
        for (int nt = 0; nt < 4; nt++) {
            int row = bm + m_base + mt * 16 + er;
            int col = bn + n_base + nt * 8 + ec;
            #pragma unroll
            for (int half = 0; half < 2; half++) {
                int r2 = row + half * 8;
                float vx = acc[mt][nt][half * 2 + 0];
                float vy = acc[mt][nt][half * 2 + 1];
                if (Res) {
                    float2 rr = *(const float2*)(Res + (size_t)r2 * N + col);
                    vx += rr.x; vy += rr.y;
                }
                if (GELU) { vx = gelu_exact(vx); vy = gelu_exact(vy); }
                store2(C + (size_t)r2 * N + col, vx * scale, vy * scale);
            }
        }
    }
}

// ---------------- Flash attention, fp16 MMA, 128-row q-tiles, 2-stage K/V ----
#define AROWB 144                  // bytes per smem row (64 halves + pad)
#define QT 128
#define KVSTG (128*AROWB)          // one stage: K 64 rows + V 64 rows
#define ATT_SMEM (QT*AROWB + 2*KVSTG)

__global__ void __launch_bounds__(256) attn_mma_kernel(
    const __half* __restrict__ Q, const __half* __restrict__ K,
    const __half* __restrict__ V, __half* __restrict__ O)
{
    extern __shared__ char asm_[];
    unsigned sb = smem_u32(asm_);
    unsigned qBase = sb;                       // 128 rows (Q, later P)
    unsigned kvBase = sb + QT * AROWB;         // 2 stages of [K 64 | V 64]

    int qt = gridDim.x - 1 - blockIdx.x;       // heavy tiles first
    int bh = blockIdx.y;
    int b = bh >> 4, h = bh & 15;
    int tid = threadIdx.x, lane = tid & 31, w = tid >> 5;   // w 0..7
    int fr = lane >> 2, fc = lane & 3;

    const __half* Qp = Q + (size_t)b * SEQ * DMODEL + h * HDIM;
    const __half* Kp = K + (size_t)b * SEQ * DMODEL + h * HDIM;
    const __half* Vp = V + (size_t)b * SEQ * DMODEL + h * HDIM;
    __half*       Op = O + (size_t)b * SEQ * DMODEL + h * HDIM;

    // fragment address offsets within one stage
    unsigned qAddr = qBase + (w * 16 + (lane & 15)) * AROWB + ((lane >> 4) << 4); // A pat
    unsigned kSel  = ((lane & 7) + (((lane >> 4) & 1) << 3)) * AROWB
                     + (((lane >> 3) & 1) << 4);                                  // B pat
    unsigned vSel  = 64 * AROWB + (lane & 15) * AROWB + ((lane >> 4) << 4);       // B-trans pat

    // stage Q tile (128 rows x 128B)
    #pragma unroll
    for (int i = 0; i < 4; i++) {
        int c = i * 256 + tid;
        int row = c >> 3, kc = c & 7;
        cpasync16(qBase + row * AROWB + kc * 16,
                  Qp + (size_t)(qt * QT + row) * DMODEL + kc * 8);
    }
    CP_COMMIT; CP_WAIT0;
    __syncthreads();

    unsigned qa[4][4];
    #pragma unroll
    for (int ks = 0; ks < 4; ks++)
        ldsm4(qa[ks][0], qa[ks][1], qa[ks][2], qa[ks][3], qAddr + ks * 32);

    float o[8][4];
    #pragma unroll
    for (int nt = 0; nt < 8; nt++)
        #pragma unroll
        for (int e = 0; e < 4; e++) o[nt][e] = 0.f;
    float mrun0 = -INFINITY, mrun1 = -INFINITY, l0 = 0.f, l1 = 0.f;

    __half* prow = (__half*)(asm_) + (w * 16 + fr) * (AROWB / 2);

    // K/V tile staging: thread covers 2 chunks of K and 2 of V
    auto stage_kv = [&](int kt, int st) {
        unsigned base = kvBase + st * KVSTG;
        #pragma unroll
        for (int i = 0; i < 2; i++) {
            int c = i * 256 + tid;
            int row = c >> 3, kc = c & 7;
            cpasync16(base + row * AROWB + kc * 16,
                      Kp + (size_t)(kt * 64 + row) * DMODEL + kc * 8);
            cpasync16(base + 64 * AROWB + row * AROWB + kc * 16,
                      Vp + (size_t)(kt * 64 + row) * DMODEL + kc * 8);
        }
    };

    int kmax = 2 * qt + 1;
    stage_kv(0, 0); CP_COMMIT;

    for (int kt = 0; kt <= kmax; kt++) {
        __syncthreads();    // tile kt-1 reads done -> buf (kt+1)&1 reusable
        if (kt < kmax) stage_kv(kt + 1, (kt + 1) & 1);
        CP_COMMIT;
        CP_WAIT1;           // tile kt landed
        __syncthreads();

        unsigned stBase = kvBase + (kt & 1) * KVSTG;
        unsigned kAddr = stBase + kSel;
        unsigned vAddr = stBase + vSel;

        // S = Q @ K^T  (16 q-rows x 64 keys per warp)
        float sc[8][4];
        #pragma unroll
        for (int nt = 0; nt < 8; nt++)
            #pragma unroll
            for (int e = 0; e < 4; e++) sc[nt][e] = 0.f;
        #pragma unroll
        for (int ks = 0; ks < 4; ks++) {
            #pragma unroll
            for (int ntp = 0; ntp < 4; ntp++) {
                unsigned b0, b1, b2, b3;
                ldsm4(b0, b1, b2, b3, kAddr + ntp * 16 * AROWB + ks * 32);
                mma_f16(sc[2 * ntp + 0], qa[ks][0], qa[ks][1], qa[ks][2], qa[ks][3], b0, b1);
                mma_f16(sc[2 * ntp + 1], qa[ks][0], qa[ks][1], qa[ks][2], qa[ks][3], b2, b3);
            }
        }

        // causal mask (only last two k-tiles can clip), global indices
        if (kt >= 2 * qt) {
            int qg0 = qt * QT + w * 16 + fr, qg1 = qg0 + 8;
            int kb0 = kt * 64;
            #pragma unroll
            for (int nt = 0; nt < 8; nt++) {
                int kg = kb0 + nt * 8 + 2 * fc;
                if (kg     > qg0) sc[nt][0] = -INFINITY;
                if (kg + 1 > qg0) sc[nt][1] = -INFINITY;
                if (kg     > qg1) sc[nt][2] = -INFINITY;
                if (kg + 1 > qg1) sc[nt][3] = -INFINITY;
            }
        }

        // online softmax
        float m0 = -INFINITY, m1 = -INFINITY;
        #pragma unroll
        for (int nt = 0; nt < 8; nt++) {
            m0 = fmaxf(m0, fmaxf(sc[nt][0], sc[nt][1]));
            m1 = fmaxf(m1, fmaxf(sc[nt][2], sc[nt][3]));
        }
        m0 = fmaxf(m0, __shfl_xor_sync(0xffffffffu, m0, 1));
        m0 = fmaxf(m0, __shfl_xor_sync(0xffffffffu, m0, 2));
        m1 = fmaxf(m1, __shfl_xor_sync(0xffffffffu, m1, 1));
        m1 = fmaxf(m1, __shfl_xor_sync(0xffffffffu, m1, 2));
        float mn0 = fmaxf(mrun0, m0), mn1 = fmaxf(mrun1, m1);
        float corr0 = __expf(mrun0 - mn0), corr1 = __expf(mrun1 - mn1);
        l0 *= corr0; l1 *= corr1;
        #pragma unroll
        for (int nt = 0; nt < 8; nt++) {
            o[nt][0] *= corr0; o[nt][1] *= corr0;
            o[nt][2] *= corr1; o[nt][3] *= corr1;
        }
        #pragma unroll
        for (int nt = 0; nt < 8; nt++) {
            float p0 = __expf(sc[nt][0] - mn0);
            float p1 = __expf(sc[nt][1] - mn0);
            float p2 = __expf(sc[nt][2] - mn1);
            float p3 = __expf(sc[nt][3] - mn1);
            l0 += p0 + p1; l1 += p2 + p3;
            __half* pp = prow + nt * 8 + 2 * fc;
            *(unsigned*)pp = packh2(p0, p1);
            *(unsigned*)(pp + 8 * (AROWB / 2)) = packh2(p2, p3);
        }
        mrun0 = mn0; mrun1 = mn1;
        __syncwarp();

        // O += P @ V  (P warp-local in Q block; V via ldmatrix.trans)
        #pragma unroll
        for (int ks = 0; ks < 4; ks++) {
            unsigned a0, a1, a2, a3;
            ldsm4(a0, a1, a2, a3, qAddr + ks * 32);
            #pragma unroll
            for (int ntp = 0; ntp < 4; ntp++) {
                unsigned b0, b1, b2, b3;
                ldsm4t(b0, b1, b2, b3, vAddr + ks * 16 * AROWB + ntp * 32);
                mma_f16(o[2 * ntp + 0], a0, a1, a2, a3, b0, b1);
                mma_f16(o[2 * ntp + 1], a0, a1, a2, a3, b2, b3);
            }
        }
        __syncwarp();   // PV reads done before next tile overwrites P
    }

    l0 += __shfl_xor_sync(0xffffffffu, l0, 1);
    l0 += __shfl_xor_sync(0xffffffffu, l0, 2);
    l1 += __shfl_xor_sync(0xffffffffu, l1, 1);
    l1 += __shfl_xor_sync(0xffffffffu, l1, 2);
    float inv0 = 1.f / l0, inv1 = 1.f / l1;

    int r0 = qt * QT + w * 16 + fr;
    __half* op0 = Op + (size_t)r0 * DMODEL;
    __half* op1 = op0 + 8 * DMODEL;
    #pragma unroll
    for (int nt = 0; nt < 8; nt++) {
        int c = nt * 8 + 2 * fc;
        *(unsigned*)(op0 + c) = packh2(o[nt][0] * inv0, o[nt][1] * inv0);
        *(unsigned*)(op1 + c) = packh2(o[nt][2] * inv1, o[nt][3] * inv1);
    }
}

// ---------------- launch ----------------
extern "C" void kernel_launch(void* const* d_in, const int* in_sizes, int n_in,
                              void* d_out, int out_size)
{
    const float* x     = (const float*)d_in[0];
    const float* Wq    = (const float*)d_in[1];
    const float* Wk    = (const float*)d_in[2];
    const float* Wv    = (const float*)d_in[3];
    const float* Wo    = (const float*)d_in[4];
    const float* Wup   = (const float*)d_in[5];
    const float* Wdown = (const float*)d_in[6];
    const float* ln1m  = (const float*)d_in[7];
    const float* ln1s  = (const float*)d_in[8];
    const float* ln2m  = (const float*)d_in[9];
    const float* ln2s  = (const float*)d_in[10];
    float* out = (float*)d_out;

    __half *ln, *q, *k, *v, *pre, *mid;
    __half *wq, *wk, *wv, *wo, *wu, *wd;
    float *x1;
    cudaGetSymbolAddress((void**)&ln,  h_ln);
    cudaGetSymbolAddress((void**)&q,   h_q);
    cudaGetSymbolAddress((void**)&k,   h_k);
    cudaGetSymbolAddress((void**)&v,   h_v);
    cudaGetSymbolAddress((void**)&pre, h_pre);
    cudaGetSymbolAddress((void**)&mid, h_mid);
    cudaGetSymbolAddress((void**)&x1,  g_x1);
    cudaGetSymbolAddress((void**)&wq,  h_wq);
    cudaGetSymbolAddress((void**)&wk,  h_wk);
    cudaGetSymbolAddress((void**)&wv,  h_wv);
    cudaGetSymbolAddress((void**)&wo,  h_wo);
    cudaGetSymbolAddress((void**)&wu,  h_wu);
    cudaGetSymbolAddress((void**)&wd,  h_wd);

    cudaFuncSetAttribute(gemm_f16_kernel<0,__half>, cudaFuncAttributeMaxDynamicSharedMemorySize, GEMM_SMEM);
    cudaFuncSetAttribute(gemm_f16_kernel<1,__half>, cudaFuncAttributeMaxDynamicSharedMemorySize, GEMM_SMEM);
    cudaFuncSetAttribute(gemm_f16_kernel<0,float>,  cudaFuncAttributeMaxDynamicSharedMemorySize, GEMM_SMEM);
    cudaFuncSetAttribute(attn_mma_kernel,           cudaFuncAttributeMaxDynamicSharedMemorySize, ATT_SMEM);

    // convert weights to fp16: one launch for the 4 DxD, one for the 2 DxDFF
    const int DD8 = DMODEL * DMODEL / 8, DF8 = DFF * DMODEL / 8;
    f32_to_f16_multi<<<dim3((DD8 + 255) / 256, 4), 256>>>(
        (const float4*)Wq, (const float4*)Wk, (const float4*)Wv, (const float4*)Wo,
        (uint4*)wq, (uint4*)wk, (uint4*)wv, (uint4*)wo, DD8);
    f32_to_f16_multi<<<dim3((DF8 + 255) / 256, 2), 256>>>(
        (const float4*)Wup, (const float4*)Wdown, nullptr, nullptr,
        (uint4*)wu, (uint4*)wd, nullptr, nullptr, DF8);

    // LN1 -> fp16
    ln_kernel<<<MTOK, 256>>>(x, ln1m, ln1s, ln);

    // Q (x 1/sqrt(hd) folded), K, V projections -> fp16
    dim3 gD(DMODEL / 128, MTOK / 128);
    gemm_f16_kernel<0,__half><<<gD, 256, GEMM_SMEM>>>(ln, wq, nullptr, q, MTOK, DMODEL, DMODEL, 0.125f);
    gemm_f16_kernel<0,__half><<<gD, 256, GEMM_SMEM>>>(ln, wk, nullptr, k, MTOK, DMODEL, DMODEL, 1.f);
    gemm_f16_kernel<0,__half><<<gD, 256, GEMM_SMEM>>>(ln, wv, nullptr, v, MTOK, DMODEL, DMODEL, 1.f);

    // causal flash attention -> fp16
    attn_mma_kernel<<<dim3(SEQ / QT, BATCH * NHEADS), 256, ATT_SMEM>>>(q, k, v, pre);

    // output projection + residual -> fp32 x1
    gemm_f16_kernel<0,float><<<gD, 256, GEMM_SMEM>>>(pre, wo, x, x1, MTOK, DMODEL, DMODEL, 1.f);

    // LN2 -> fp16
    ln_kernel<<<MTOK, 256>>>(x1, ln2m, ln2s, ln);

    // MLP up + exact GELU -> fp16
    dim3 gUp(DFF / 128, MTOK / 128);
    gemm_f16_kernel<1,__half><<<gUp, 256, GEMM_SMEM>>>(ln, wu, nullptr, mid, MTOK, DFF, DMODEL, 1.f);

    // MLP down + residual -> fp32 output
    gemm_f16_kernel<0,float><<<gD, 256, GEMM_SMEM>>>(mid, wd, x1, out, MTOK, DMODEL, DFF, 1.f);
}